// round 1
// baseline (speedup 1.0000x reference)
#include <cuda_runtime.h>
#include <math.h>

#define BB  2
#define SS  2048
#define DM  1024
#define NH  16
#define DKK 64

// Scratch (allocation-free rule: __device__ globals)
__device__ float g_Qh[BB*NH*SS*DKK];   // [b][h][s][dk]
__device__ float g_Kh[BB*NH*SS*DKK];
__device__ float g_Vh[BB*NH*SS*DKK];
__device__ float g_Oh[BB*SS*DM];       // [b][s][h*64+dk]

// ---------------------------------------------------------------------------
// Y[m][n] = sum_k X[m][k] * W[n][k] + bias[n]
// X: [M=4096, K=1024] row-major, W: [N=1024, K=1024] row-major.
// head_split=1: write Y to [b][h][s][dk] layout; else plain row-major [m][n].
// 128x128 tile, BK=16, 256 threads, 8x8 per thread.
// ---------------------------------------------------------------------------
__global__ __launch_bounds__(256, 2)
void gemm_xwT(const float* __restrict__ X, const float* __restrict__ W,
              const float* __restrict__ bias, float* __restrict__ Y,
              int head_split)
{
    __shared__ float As[16][128];
    __shared__ float Bs[16][128];
    const int bm = blockIdx.y * 128;
    const int bn = blockIdx.x * 128;
    const int tid = threadIdx.x;
    const int tx = tid & 15, ty = tid >> 4;

    float acc[8][8];
    #pragma unroll
    for (int i = 0; i < 8; i++)
        #pragma unroll
        for (int j = 0; j < 8; j++) acc[i][j] = 0.f;

    for (int k0 = 0; k0 < DM; k0 += 16) {
        #pragma unroll
        for (int it = 0; it < 2; it++) {
            int v = tid + it * 256;             // 0..511 float4 slots
            int row = v >> 2, c4 = v & 3;
            float4 d = *(const float4*)(X + (size_t)(bm + row) * DM + k0 + c4 * 4);
            As[c4*4+0][row] = d.x; As[c4*4+1][row] = d.y;
            As[c4*4+2][row] = d.z; As[c4*4+3][row] = d.w;
        }
        #pragma unroll
        for (int it = 0; it < 2; it++) {
            int v = tid + it * 256;
            int row = v >> 2, c4 = v & 3;
            float4 d = *(const float4*)(W + (size_t)(bn + row) * DM + k0 + c4 * 4);
            Bs[c4*4+0][row] = d.x; Bs[c4*4+1][row] = d.y;
            Bs[c4*4+2][row] = d.z; Bs[c4*4+3][row] = d.w;
        }
        __syncthreads();
        #pragma unroll
        for (int k = 0; k < 16; k++) {
            float a[8], b[8];
            #pragma unroll
            for (int i = 0; i < 8; i++) a[i] = As[k][ty*8 + i];
            #pragma unroll
            for (int j = 0; j < 8; j++) b[j] = Bs[k][tx*8 + j];
            #pragma unroll
            for (int i = 0; i < 8; i++)
                #pragma unroll
                for (int j = 0; j < 8; j++)
                    acc[i][j] = fmaf(a[i], b[j], acc[i][j]);
        }
        __syncthreads();
    }

    #pragma unroll
    for (int i = 0; i < 8; i++) {
        int m = bm + ty*8 + i;
        int b_ = m / SS, s_ = m % SS;
        #pragma unroll
        for (int j = 0; j < 8; j++) {
            int n = bn + tx*8 + j;
            float val = acc[i][j] + bias[n];
            if (head_split) {
                int h_ = n >> 6, dk = n & 63;
                Y[(((size_t)b_ * NH + h_) * SS + s_) * DKK + dk] = val;
            } else {
                Y[(size_t)m * DM + n] = val;
            }
        }
    }
}

// ---------------------------------------------------------------------------
// Flash attention (fp32, online softmax).
// Block: 256 threads, one (b, h, 64-row q tile). K tiles of 32 rows.
// grid = (S/64, NH, B)
// ---------------------------------------------------------------------------
__global__ __launch_bounds__(256)
void flash_attn(const int* __restrict__ q_mask, const int* __restrict__ k_mask,
                const int* __restrict__ causal_flag, int causal_default,
                float* __restrict__ Oh)
{
    __shared__ float Qs[64][65];
    __shared__ float Ks[32][65];
    __shared__ float Vs[32][64];
    __shared__ float Ps[64][33];
    __shared__ float m_s[64], l_s[64], alpha_s[64];
    __shared__ int   kmask_s[32];

    const int b  = blockIdx.z, h = blockIdx.y;
    const int q0 = blockIdx.x * 64;
    const int tid = threadIdx.x;
    const int tx = tid & 15, ty = tid >> 4;
    const int lane = tid & 31, wid = tid >> 5;
    const int causal = causal_flag ? causal_flag[0] : causal_default;

    const float* Qbase = g_Qh + (((size_t)b * NH + h) * SS) * DKK;
    const float* Kbase = g_Kh + (((size_t)b * NH + h) * SS) * DKK;
    const float* Vbase = g_Vh + (((size_t)b * NH + h) * SS) * DKK;

    // Q tile: 64x64 floats = 1024 float4
    #pragma unroll
    for (int it = 0; it < 4; it++) {
        int v = tid + it * 256;
        int row = v >> 4, c4 = v & 15;
        float4 d = *(const float4*)(Qbase + (size_t)(q0 + row) * DKK + c4 * 4);
        Qs[row][c4*4+0] = d.x; Qs[row][c4*4+1] = d.y;
        Qs[row][c4*4+2] = d.z; Qs[row][c4*4+3] = d.w;
    }
    if (tid < 64) { m_s[tid] = -INFINITY; l_s[tid] = 0.f; }

    float acc[4][4];
    #pragma unroll
    for (int i = 0; i < 4; i++)
        #pragma unroll
        for (int j = 0; j < 4; j++) acc[i][j] = 0.f;

    int nkt = SS / 32;
    if (causal) nkt = q0 / 32 + 2;   // only tiles with k0 <= q0+63

    for (int kt = 0; kt < nkt; kt++) {
        int k0 = kt * 32;
        __syncthreads();  // protect smem from previous iteration's readers

        #pragma unroll
        for (int it = 0; it < 2; it++) {
            int v = tid + it * 256;          // 0..511 float4 slots (32x16)
            int row = v >> 4, c4 = v & 15;
            float4 d = *(const float4*)(Kbase + (size_t)(k0 + row) * DKK + c4 * 4);
            Ks[row][c4*4+0] = d.x; Ks[row][c4*4+1] = d.y;
            Ks[row][c4*4+2] = d.z; Ks[row][c4*4+3] = d.w;
            float4 e = *(const float4*)(Vbase + (size_t)(k0 + row) * DKK + c4 * 4);
            *(float4*)&Vs[row][c4*4] = e;
        }
        if (tid < 32) kmask_s[tid] = k_mask[(size_t)b * SS + k0 + tid];
        __syncthreads();

        // S = Q K^T : each thread 4 q-rows x 2 k-cols
        float sv[4][2];
        #pragma unroll
        for (int i = 0; i < 4; i++) { sv[i][0] = 0.f; sv[i][1] = 0.f; }
        #pragma unroll 16
        for (int d = 0; d < 64; d++) {
            float a0 = Qs[ty*4+0][d], a1 = Qs[ty*4+1][d];
            float a2 = Qs[ty*4+2][d], a3 = Qs[ty*4+3][d];
            float b0 = Ks[tx*2+0][d], b1 = Ks[tx*2+1][d];
            sv[0][0] = fmaf(a0, b0, sv[0][0]); sv[0][1] = fmaf(a0, b1, sv[0][1]);
            sv[1][0] = fmaf(a1, b0, sv[1][0]); sv[1][1] = fmaf(a1, b1, sv[1][1]);
            sv[2][0] = fmaf(a2, b0, sv[2][0]); sv[2][1] = fmaf(a2, b1, sv[2][1]);
            sv[3][0] = fmaf(a3, b0, sv[3][0]); sv[3][1] = fmaf(a3, b1, sv[3][1]);
        }
        #pragma unroll
        for (int i = 0; i < 4; i++) {
            int qg = q0 + ty*4 + i;
            #pragma unroll
            for (int j = 0; j < 2; j++) {
                int kc = tx*2 + j;
                int kg = k0 + kc;
                float x = sv[i][j] * 0.125f;   // 1/sqrt(64)
                if ((causal && kg > qg) || kmask_s[kc] == 0) x = -INFINITY;
                Ps[ty*4+i][kc] = x;
            }
        }
        __syncthreads();

        // Online softmax: 4 lanes per row, 8 rows per warp
        {
            int row = wid * 8 + (lane >> 2);
            int cq  = lane & 3;
            float mx = -INFINITY;
            #pragma unroll
            for (int t = 0; t < 8; t++) mx = fmaxf(mx, Ps[row][cq + 4*t]);
            mx = fmaxf(mx, __shfl_xor_sync(0xffffffffu, mx, 1, 4));
            mx = fmaxf(mx, __shfl_xor_sync(0xffffffffu, mx, 2, 4));
            float m_old = m_s[row];
            float m_new = fmaxf(m_old, mx);
            float sum = 0.f;
            #pragma unroll
            for (int t = 0; t < 8; t++) {
                float p = __expf(Ps[row][cq + 4*t] - m_new);
                Ps[row][cq + 4*t] = p;
                sum += p;
            }
            sum += __shfl_xor_sync(0xffffffffu, sum, 1, 4);
            sum += __shfl_xor_sync(0xffffffffu, sum, 2, 4);
            float alpha = __expf(m_old - m_new);   // NaN if both -inf (matches ref)
            if (cq == 0) {
                m_s[row] = m_new;
                l_s[row] = l_s[row] * alpha + sum;
                alpha_s[row] = alpha;
            }
        }
        __syncthreads();

        // O = O*alpha + P @ V : each thread 4 q-rows x 4 dk-cols
        #pragma unroll
        for (int i = 0; i < 4; i++) {
            float al = alpha_s[ty*4 + i];
            #pragma unroll
            for (int j = 0; j < 4; j++) acc[i][j] *= al;
        }
        #pragma unroll 8
        for (int kk = 0; kk < 32; kk++) {
            float p0 = Ps[ty*4+0][kk], p1 = Ps[ty*4+1][kk];
            float p2 = Ps[ty*4+2][kk], p3 = Ps[ty*4+3][kk];
            float4 v4 = *(const float4*)&Vs[kk][tx*4];
            acc[0][0] = fmaf(p0, v4.x, acc[0][0]); acc[0][1] = fmaf(p0, v4.y, acc[0][1]);
            acc[0][2] = fmaf(p0, v4.z, acc[0][2]); acc[0][3] = fmaf(p0, v4.w, acc[0][3]);
            acc[1][0] = fmaf(p1, v4.x, acc[1][0]); acc[1][1] = fmaf(p1, v4.y, acc[1][1]);
            acc[1][2] = fmaf(p1, v4.z, acc[1][2]); acc[1][3] = fmaf(p1, v4.w, acc[1][3]);
            acc[2][0] = fmaf(p2, v4.x, acc[2][0]); acc[2][1] = fmaf(p2, v4.y, acc[2][1]);
            acc[2][2] = fmaf(p2, v4.z, acc[2][2]); acc[2][3] = fmaf(p2, v4.w, acc[2][3]);
            acc[3][0] = fmaf(p3, v4.x, acc[3][0]); acc[3][1] = fmaf(p3, v4.y, acc[3][1]);
            acc[3][2] = fmaf(p3, v4.z, acc[3][2]); acc[3][3] = fmaf(p3, v4.w, acc[3][3]);
        }
    }

    // Epilogue: normalize, apply q_mask (zero overrides NaN, matching reference)
    #pragma unroll
    for (int i = 0; i < 4; i++) {
        int s_ = q0 + ty*4 + i;
        int qm = q_mask[(size_t)b * SS + s_];
        float inv_l = 1.f / l_s[ty*4 + i];   // NaN rows propagate naturally
        float4 o;
        if (qm == 0) {
            o = make_float4(0.f, 0.f, 0.f, 0.f);
        } else {
            o.x = acc[i][0] * inv_l; o.y = acc[i][1] * inv_l;
            o.z = acc[i][2] * inv_l; o.w = acc[i][3] * inv_l;
        }
        *(float4*)(Oh + ((size_t)b * SS + s_) * DM + h * DKK + tx * 4) = o;
    }
}

// ---------------------------------------------------------------------------
extern "C" void kernel_launch(void* const* d_in, const int* in_sizes, int n_in,
                              void* d_out, int out_size)
{
    const float* q  = (const float*)d_in[0];
    const float* k  = (const float*)d_in[1];
    const int*   qm = (const int*)  d_in[2];
    const int*   km = (const int*)  d_in[3];
    const float* Wq = (const float*)d_in[4];
    const float* bq = (const float*)d_in[5];
    const float* Wk = (const float*)d_in[6];
    const float* bk = (const float*)d_in[7];
    const float* Wv = (const float*)d_in[8];
    const float* bv = (const float*)d_in[9];
    const float* Wo = (const float*)d_in[10];
    const float* bo = (const float*)d_in[11];
    const int* causal = (n_in >= 13) ? (const int*)d_in[12] : nullptr;

    float *Qh, *Kh, *Vh, *Oh;
    cudaGetSymbolAddress((void**)&Qh, g_Qh);
    cudaGetSymbolAddress((void**)&Kh, g_Kh);
    cudaGetSymbolAddress((void**)&Vh, g_Vh);
    cudaGetSymbolAddress((void**)&Oh, g_Oh);

    dim3 gg(DM / 128, (BB * SS) / 128);   // (8, 32)
    gemm_xwT<<<gg, 256>>>(q, Wq, bq, Qh, 1);
    gemm_xwT<<<gg, 256>>>(k, Wk, bk, Kh, 1);
    gemm_xwT<<<gg, 256>>>(k, Wv, bv, Vh, 1);

    dim3 ga(SS / 64, NH, BB);             // (32, 16, 2)
    flash_attn<<<ga, 256>>>(qm, km, causal, 1, Oh);

    gemm_xwT<<<gg, 256>>>(Oh, Wo, bo, (float*)d_out, 0);
}

// round 2
// speedup vs baseline: 3.6056x; 3.6056x over previous
#include <cuda_runtime.h>
#include <math.h>
#include <stdint.h>

#define BB  2
#define SS  2048
#define DM  1024
#define NH  16
#define DKK 64

// Scratch (allocation-free rule: __device__ globals)
__device__ float g_Qh[BB*NH*SS*DKK];   // [b][h][s][dk]
__device__ float g_Kh[BB*NH*SS*DKK];
__device__ float g_Vh[BB*NH*SS*DKK];
__device__ float g_Oh[BB*SS*DM];       // [b][s][h*64+dk]

// ---------------------------------------------------------------------------
// tf32 helpers
// ---------------------------------------------------------------------------
__device__ __forceinline__ uint32_t f2tf(float x) {
    uint32_t u;
    asm("cvt.rna.tf32.f32 %0, %1;" : "=r"(u) : "f"(x));
    return u;
}

__device__ __forceinline__ void mma_tf32(float c[4], const uint32_t a[4], const uint32_t b[2]) {
    asm volatile(
        "mma.sync.aligned.m16n8k8.row.col.f32.tf32.tf32.f32 "
        "{%0,%1,%2,%3}, {%4,%5,%6,%7}, {%8,%9}, {%0,%1,%2,%3};\n"
        : "+f"(c[0]), "+f"(c[1]), "+f"(c[2]), "+f"(c[3])
        : "r"(a[0]), "r"(a[1]), "r"(a[2]), "r"(a[3]), "r"(b[0]), "r"(b[1]));
}

// ---------------------------------------------------------------------------
// tf32 tensor-core GEMM: Y[m][n] = sum_k X[m][k]*W[n][k] + bias[n]
// X: [M=4096,K=1024] row-major, W: [N=1024,K=1024] row-major.
// Block 128x128, BK=32, 256 threads (8 warps as 4x2; warp tile 32x64).
// tf32 conversion (RNA) applied once at smem-store time.
// head_split=1: write Y to [b][h][s][dk] layout; else row-major [m][n].
// ---------------------------------------------------------------------------
__global__ __launch_bounds__(256, 2)
void gemm_tf32(const float* __restrict__ X, const float* __restrict__ W,
               const float* __restrict__ bias, float* __restrict__ Y,
               int head_split)
{
    __shared__ float As[128][36];   // tf32 bit patterns stored as float
    __shared__ float Bs[128][36];

    const int bm = blockIdx.y * 128;
    const int bn = blockIdx.x * 128;
    const int tid = threadIdx.x;
    const int lane = tid & 31, wid = tid >> 5;
    const int wm = wid >> 1;        // 0..3  (m offset wm*32)
    const int wn = wid & 1;         // 0..1  (n offset wn*64)
    const int grp = lane >> 2;      // 0..7
    const int tig = lane & 3;       // 0..3

    float c[2][8][4];
    #pragma unroll
    for (int t = 0; t < 2; t++)
        #pragma unroll
        for (int u = 0; u < 8; u++)
            #pragma unroll
            for (int r = 0; r < 4; r++) c[t][u][r] = 0.f;

    for (int k0 = 0; k0 < DM; k0 += 32) {
        // load X tile 128x32 (coalesced: 8 lanes per row) -> tf32 -> As
        #pragma unroll
        for (int i = 0; i < 4; i++) {
            int v = tid + i * 256;
            int row = v >> 3, c4 = v & 7;
            float4 d = *(const float4*)(X + (size_t)(bm + row) * DM + k0 + c4 * 4);
            float4 e;
            e.x = __uint_as_float(f2tf(d.x)); e.y = __uint_as_float(f2tf(d.y));
            e.z = __uint_as_float(f2tf(d.z)); e.w = __uint_as_float(f2tf(d.w));
            *(float4*)&As[row][c4 * 4] = e;
        }
        #pragma unroll
        for (int i = 0; i < 4; i++) {
            int v = tid + i * 256;
            int row = v >> 3, c4 = v & 7;
            float4 d = *(const float4*)(W + (size_t)(bn + row) * DM + k0 + c4 * 4);
            float4 e;
            e.x = __uint_as_float(f2tf(d.x)); e.y = __uint_as_float(f2tf(d.y));
            e.z = __uint_as_float(f2tf(d.z)); e.w = __uint_as_float(f2tf(d.w));
            *(float4*)&Bs[row][c4 * 4] = e;
        }
        __syncthreads();

        #pragma unroll
        for (int s = 0; s < 4; s++) {
            uint32_t a[2][4];
            uint32_t b[8][2];
            const int cc = s * 8 + tig;
            #pragma unroll
            for (int t = 0; t < 2; t++) {
                int r = wm * 32 + t * 16 + grp;
                a[t][0] = __float_as_uint(As[r    ][cc]);
                a[t][1] = __float_as_uint(As[r + 8][cc]);
                a[t][2] = __float_as_uint(As[r    ][cc + 4]);
                a[t][3] = __float_as_uint(As[r + 8][cc + 4]);
            }
            #pragma unroll
            for (int u = 0; u < 8; u++) {
                int n = wn * 64 + u * 8 + grp;
                b[u][0] = __float_as_uint(Bs[n][cc]);
                b[u][1] = __float_as_uint(Bs[n][cc + 4]);
            }
            #pragma unroll
            for (int t = 0; t < 2; t++)
                #pragma unroll
                for (int u = 0; u < 8; u++)
                    mma_tf32(c[t][u], a[t], b[u]);
        }
        __syncthreads();
    }

    // epilogue
    #pragma unroll
    for (int t = 0; t < 2; t++) {
        #pragma unroll
        for (int u = 0; u < 8; u++) {
            int r0  = bm + wm * 32 + t * 16 + grp;
            int col = bn + wn * 64 + u * 8 + 2 * tig;
            float b0 = bias[col], b1 = bias[col + 1];
            #pragma unroll
            for (int half = 0; half < 2; half++) {
                int m = r0 + half * 8;
                float2 o;
                o.x = c[t][u][half * 2 + 0] + b0;
                o.y = c[t][u][half * 2 + 1] + b1;
                if (head_split) {
                    int b_ = m >> 11, s_ = m & 2047;
                    int h_ = col >> 6, dk = col & 63;
                    *(float2*)(Y + (((size_t)b_ * NH + h_) * SS + s_) * DKK + dk) = o;
                } else {
                    *(float2*)(Y + (size_t)m * DM + col) = o;
                }
            }
        }
    }
}

// ---------------------------------------------------------------------------
// Flash attention with tf32 tensor cores + smem-staged online softmax.
// Block: 128 threads (4 warps, 2x2), tile Sq=64 x Sk=64, d_k=64.
// bufA: Q raw -> scores -> probs(tf32).  bufB: K(tf32) -> V(tf32).
// grid = (S/64, NH, B)
// ---------------------------------------------------------------------------
__global__ __launch_bounds__(128)
void flash_attn_tc(const int* __restrict__ q_mask, const int* __restrict__ k_mask,
                   const int* __restrict__ causal_flag, int causal_default)
{
    __shared__ float bufA[64][68];
    __shared__ float bufB[64][68];
    __shared__ float m_s[64], l_s[64], alpha_s[64];
    __shared__ int   kmask_s[64];

    const int b  = blockIdx.z, h = blockIdx.y;
    const int q0 = blockIdx.x * 64;
    const int tid = threadIdx.x;
    const int lane = tid & 31, wid = tid >> 5;
    const int wm = wid >> 1;      // 0..1 : q rows [wm*32, wm*32+32)
    const int wn = wid & 1;       // 0..1 : k cols / d cols [wn*32, +32)
    const int grp = lane >> 2;    // 0..7
    const int tig = lane & 3;     // 0..3
    const int causal = causal_flag ? causal_flag[0] : causal_default;

    const float* Qb = g_Qh + (((size_t)b * NH + h) * SS) * DKK;
    const float* Kb = g_Kh + (((size_t)b * NH + h) * SS) * DKK;
    const float* Vb = g_Vh + (((size_t)b * NH + h) * SS) * DKK;

    // ---- load Q tile (raw fp32) ----
    #pragma unroll
    for (int i = 0; i < 8; i++) {
        int v = tid + i * 128;
        int row = v >> 4, c4 = v & 15;
        float4 d = *(const float4*)(Qb + (size_t)(q0 + row) * DKK + c4 * 4);
        *(float4*)&bufA[row][c4 * 4] = d;
    }
    if (tid < 64) { m_s[tid] = -INFINITY; l_s[tid] = 0.f; }
    __syncthreads();

    // ---- extract Q fragments (tf32, resident in registers) ----
    uint32_t qf[8][2][4];
    #pragma unroll
    for (int s8 = 0; s8 < 8; s8++) {
        #pragma unroll
        for (int t = 0; t < 2; t++) {
            int r = wm * 32 + t * 16 + grp;
            int cc = s8 * 8 + tig;
            qf[s8][t][0] = f2tf(bufA[r    ][cc]);
            qf[s8][t][1] = f2tf(bufA[r + 8][cc]);
            qf[s8][t][2] = f2tf(bufA[r    ][cc + 4]);
            qf[s8][t][3] = f2tf(bufA[r + 8][cc + 4]);
        }
    }

    float o[2][4][4];
    #pragma unroll
    for (int t = 0; t < 2; t++)
        #pragma unroll
        for (int u = 0; u < 4; u++)
            #pragma unroll
            for (int r = 0; r < 4; r++) o[t][u][r] = 0.f;

    const int nkt = causal ? (q0 >> 6) + 1 : (SS / 64);

    for (int kt = 0; kt < nkt; kt++) {
        const int k0 = kt * 64;
        __syncthreads();   // bufA (Q frags read / prev probs) & bufB (prev V) free

        // ---- load K tile -> tf32 -> bufB ; kmask ----
        #pragma unroll
        for (int i = 0; i < 8; i++) {
            int v = tid + i * 128;
            int row = v >> 4, c4 = v & 15;
            float4 d = *(const float4*)(Kb + (size_t)(k0 + row) * DKK + c4 * 4);
            float4 e;
            e.x = __uint_as_float(f2tf(d.x)); e.y = __uint_as_float(f2tf(d.y));
            e.z = __uint_as_float(f2tf(d.z)); e.w = __uint_as_float(f2tf(d.w));
            *(float4*)&bufB[row][c4 * 4] = e;
        }
        if (tid < 64) kmask_s[tid] = k_mask[(size_t)b * SS + k0 + tid];
        __syncthreads();

        // ---- S = Q K^T via mma ----
        float sacc[2][4][4];
        #pragma unroll
        for (int t = 0; t < 2; t++)
            #pragma unroll
            for (int u = 0; u < 4; u++)
                #pragma unroll
                for (int r = 0; r < 4; r++) sacc[t][u][r] = 0.f;

        #pragma unroll
        for (int s8 = 0; s8 < 8; s8++) {
            uint32_t kb[4][2];
            const int cc = s8 * 8 + tig;
            #pragma unroll
            for (int u = 0; u < 4; u++) {
                int n = wn * 32 + u * 8 + grp;   // key index (B col)
                kb[u][0] = __float_as_uint(bufB[n][cc]);
                kb[u][1] = __float_as_uint(bufB[n][cc + 4]);
            }
            #pragma unroll
            for (int t = 0; t < 2; t++)
                #pragma unroll
                for (int u = 0; u < 4; u++)
                    mma_tf32(sacc[t][u], qf[s8][t], kb[u]);
        }

        // ---- scale + masks -> scores into bufA ----
        #pragma unroll
        for (int t = 0; t < 2; t++) {
            int rl0 = wm * 32 + t * 16 + grp;
            int qg0 = q0 + rl0, qg1 = qg0 + 8;
            #pragma unroll
            for (int u = 0; u < 4; u++) {
                int cl = wn * 32 + u * 8 + 2 * tig;
                int kg = k0 + cl;
                int km0 = kmask_s[cl], km1 = kmask_s[cl + 1];
                float x0 = sacc[t][u][0] * 0.125f;
                float x1 = sacc[t][u][1] * 0.125f;
                float x2 = sacc[t][u][2] * 0.125f;
                float x3 = sacc[t][u][3] * 0.125f;
                if ((causal && kg     > qg0) || km0 == 0) x0 = -INFINITY;
                if ((causal && kg + 1 > qg0) || km1 == 0) x1 = -INFINITY;
                if ((causal && kg     > qg1) || km0 == 0) x2 = -INFINITY;
                if ((causal && kg + 1 > qg1) || km1 == 0) x3 = -INFINITY;
                *(float2*)&bufA[rl0    ][cl] = make_float2(x0, x1);
                *(float2*)&bufA[rl0 + 8][cl] = make_float2(x2, x3);
            }
        }
        __syncthreads();

        // ---- online softmax on bufA (2 threads per row) + V load -> bufB ----
        {
            int row = tid >> 1, half = tid & 1, c0 = half * 32;
            float mx = -INFINITY;
            #pragma unroll
            for (int j = 0; j < 32; j++) mx = fmaxf(mx, bufA[row][c0 + j]);
            mx = fmaxf(mx, __shfl_xor_sync(0xffffffffu, mx, 1));
            float m_old = m_s[row];
            float m_new = fmaxf(m_old, mx);
            float sum = 0.f;
            #pragma unroll
            for (int j = 0; j < 32; j++) {
                float p = __expf(bufA[row][c0 + j] - m_new);
                sum += p;
                bufA[row][c0 + j] = __uint_as_float(f2tf(p));
            }
            sum += __shfl_xor_sync(0xffffffffu, sum, 1);
            float alpha = __expf(m_old - m_new);   // NaN iff both -inf (matches ref)
            if (half == 0) {
                m_s[row] = m_new;
                l_s[row] = l_s[row] * alpha + sum;
                alpha_s[row] = alpha;
            }
        }
        // V load (bufB; K fully consumed by mma above, fenced by last sync)
        #pragma unroll
        for (int i = 0; i < 8; i++) {
            int v = tid + i * 128;
            int row = v >> 4, c4 = v & 15;
            float4 d = *(const float4*)(Vb + (size_t)(k0 + row) * DKK + c4 * 4);
            float4 e;
            e.x = __uint_as_float(f2tf(d.x)); e.y = __uint_as_float(f2tf(d.y));
            e.z = __uint_as_float(f2tf(d.z)); e.w = __uint_as_float(f2tf(d.w));
            *(float4*)&bufB[row][c4 * 4] = e;
        }
        __syncthreads();

        // ---- rescale O by alpha ----
        #pragma unroll
        for (int t = 0; t < 2; t++) {
            float al0 = alpha_s[wm * 32 + t * 16 + grp];
            float al1 = alpha_s[wm * 32 + t * 16 + grp + 8];
            #pragma unroll
            for (int u = 0; u < 4; u++) {
                o[t][u][0] *= al0; o[t][u][1] *= al0;
                o[t][u][2] *= al1; o[t][u][3] *= al1;
            }
        }

        // ---- O += P @ V via mma ----
        #pragma unroll
        for (int s8 = 0; s8 < 8; s8++) {
            uint32_t pf[2][4];
            uint32_t vb[4][2];
            const int cc = s8 * 8 + tig;
            #pragma unroll
            for (int t = 0; t < 2; t++) {
                int r = wm * 32 + t * 16 + grp;
                pf[t][0] = __float_as_uint(bufA[r    ][cc]);
                pf[t][1] = __float_as_uint(bufA[r + 8][cc]);
                pf[t][2] = __float_as_uint(bufA[r    ][cc + 4]);
                pf[t][3] = __float_as_uint(bufA[r + 8][cc + 4]);
            }
            #pragma unroll
            for (int u = 0; u < 4; u++) {
                int dcol = wn * 32 + u * 8 + grp;
                int kr = s8 * 8 + tig;
                vb[u][0] = __float_as_uint(bufB[kr    ][dcol]);
                vb[u][1] = __float_as_uint(bufB[kr + 4][dcol]);
            }
            #pragma unroll
            for (int t = 0; t < 2; t++)
                #pragma unroll
                for (int u = 0; u < 4; u++)
                    mma_tf32(o[t][u], pf[t], vb[u]);
        }
    }

    // ---- epilogue: normalize, q_mask, write Oh ----
    #pragma unroll
    for (int t = 0; t < 2; t++) {
        #pragma unroll
        for (int half = 0; half < 2; half++) {
            int rl = wm * 32 + t * 16 + grp + half * 8;
            int s_ = q0 + rl;
            int qm = q_mask[(size_t)b * SS + s_];
            float inv_l = 1.f / l_s[rl];   // NaN rows propagate (matches ref)
            #pragma unroll
            for (int u = 0; u < 4; u++) {
                int dcol = wn * 32 + u * 8 + 2 * tig;
                float2 ov;
                if (qm == 0) {
                    ov = make_float2(0.f, 0.f);
                } else {
                    ov.x = o[t][u][half * 2 + 0] * inv_l;
                    ov.y = o[t][u][half * 2 + 1] * inv_l;
                }
                *(float2*)(g_Oh + ((size_t)b * SS + s_) * DM + h * DKK + dcol) = ov;
            }
        }
    }
}

// ---------------------------------------------------------------------------
extern "C" void kernel_launch(void* const* d_in, const int* in_sizes, int n_in,
                              void* d_out, int out_size)
{
    const float* q  = (const float*)d_in[0];
    const float* k  = (const float*)d_in[1];
    const int*   qm = (const int*)  d_in[2];
    const int*   km = (const int*)  d_in[3];
    const float* Wq = (const float*)d_in[4];
    const float* bq = (const float*)d_in[5];
    const float* Wk = (const float*)d_in[6];
    const float* bk = (const float*)d_in[7];
    const float* Wv = (const float*)d_in[8];
    const float* bv = (const float*)d_in[9];
    const float* Wo = (const float*)d_in[10];
    const float* bo = (const float*)d_in[11];
    const int* causal = (n_in >= 13) ? (const int*)d_in[12] : nullptr;

    float *Qh, *Kh, *Vh, *Oh;
    cudaGetSymbolAddress((void**)&Qh, g_Qh);
    cudaGetSymbolAddress((void**)&Kh, g_Kh);
    cudaGetSymbolAddress((void**)&Vh, g_Vh);
    cudaGetSymbolAddress((void**)&Oh, g_Oh);

    dim3 gg(DM / 128, (BB * SS) / 128);   // (8, 32)
    gemm_tf32<<<gg, 256>>>(q, Wq, bq, Qh, 1);
    gemm_tf32<<<gg, 256>>>(k, Wk, bk, Kh, 1);
    gemm_tf32<<<gg, 256>>>(k, Wv, bv, Vh, 1);

    dim3 ga(SS / 64, NH, BB);             // (32, 16, 2)
    flash_attn_tc<<<ga, 128>>>(qm, km, causal, 1);

    gemm_tf32<<<gg, 256>>>(Oh, Wo, bo, (float*)d_out, 0);
}